// round 4
// baseline (speedup 1.0000x reference)
#include <cuda_runtime.h>
#include <math.h>

#define T_STEPS 512
#define B_SZ    64
#define I_SZ    128
#define H_SZ    1024
#define ALPHA   0.5f

#define SCAN_BLOCKS  128
#define SCAN_THREADS 128
#define W_PITCH  1028   // 1024 + 4 pad (floats)
#define H_PITCH  260    // 256 + 4 pad (floats)
#define SMEM_SCAN_BYTES ((8 * W_PITCH + 64 * H_PITCH) * 4)

// ---- scratch (no allocations allowed; __device__ globals are the sanctioned path)
__device__ float g_U[(long)T_STEPS * B_SZ * H_SZ];   // 134 MB, reused for U0 then U1
__device__ float g_h[2][B_SZ * H_SZ];                // double-buffered recurrent state
__device__ unsigned long long g_bar;                 // monotonic grid-barrier counter

// ============================================================================
// Software grid barrier. All SCAN_BLOCKS=128 blocks of the lone running kernel
// are co-resident (128 <= 148 SMs, 1 block/SM by smem), so this cannot
// deadlock. Monotonic counter -> no reset, deterministic across graph replays.
// ============================================================================
__device__ __forceinline__ void grid_barrier() {
    __syncthreads();
    if (threadIdx.x == 0) {
        __threadfence();
        unsigned long long prev = atomicAdd(&g_bar, 1ULL);
        unsigned long long target =
            (prev / SCAN_BLOCKS + 1ULL) * (unsigned long long)SCAN_BLOCKS;
        while (*((volatile unsigned long long*)&g_bar) < target) {
            __nanosleep(32);
        }
        __threadfence();
    }
    __syncthreads();
}

// ============================================================================
// GEMM: g_U[m][n] = sum_k A[m*lda + k] * B[n*K + k]   (C = A @ B^T)
// M = 32768 (grid.y*64), N = 1024 (grid.x*64), K in {128, 1024}.
// 64x64 tile, K-chunk 32, 128 threads, 8x4 register tile per thread.
// ============================================================================
__global__ void gemm_abT(const float* __restrict__ A, int lda,
                         const float* __restrict__ Bm, int K)
{
    __shared__ float Ast[32][68];
    __shared__ float Bst[32][68];
    const int tid = threadIdx.x;
    const int m0 = blockIdx.y * 64;
    const int n0 = blockIdx.x * 64;
    const int tx = tid & 15;        // 0..15 -> n sub-tile (4 cols)
    const int ty = tid >> 4;        // 0..7  -> m sub-tile (8 rows)

    float acc[8][4] = {};

    for (int k0 = 0; k0 < K; k0 += 32) {
        #pragma unroll
        for (int i = 0; i < 4; i++) {
            int idx = tid + i * 128;           // 0..511
            int row = idx >> 3;                // 0..63
            int kq  = idx & 7;                 // float4 within k-chunk
            float4 v = *(const float4*)&A[(long)(m0 + row) * lda + k0 + kq * 4];
            Ast[kq * 4 + 0][row] = v.x;
            Ast[kq * 4 + 1][row] = v.y;
            Ast[kq * 4 + 2][row] = v.z;
            Ast[kq * 4 + 3][row] = v.w;
            float4 w = *(const float4*)&Bm[(long)(n0 + row) * K + k0 + kq * 4];
            Bst[kq * 4 + 0][row] = w.x;
            Bst[kq * 4 + 1][row] = w.y;
            Bst[kq * 4 + 2][row] = w.z;
            Bst[kq * 4 + 3][row] = w.w;
        }
        __syncthreads();
        #pragma unroll
        for (int k = 0; k < 32; k++) {
            float4 a0 = *(const float4*)&Ast[k][ty * 8];
            float4 a1 = *(const float4*)&Ast[k][ty * 8 + 4];
            float4 bv = *(const float4*)&Bst[k][tx * 4];
            float a[8] = {a0.x, a0.y, a0.z, a0.w, a1.x, a1.y, a1.z, a1.w};
            float b[4] = {bv.x, bv.y, bv.z, bv.w};
            #pragma unroll
            for (int i = 0; i < 8; i++)
                #pragma unroll
                for (int j = 0; j < 4; j++)
                    acc[i][j] += a[i] * b[j];
        }
        __syncthreads();
    }

    #pragma unroll
    for (int i = 0; i < 8; i++) {
        float4 o = make_float4(acc[i][0], acc[i][1], acc[i][2], acc[i][3]);
        *(float4*)&g_U[(long)(m0 + ty * 8 + i) * H_SZ + n0 + tx * 4] = o;
    }
}

// ============================================================================
// Persistent sequential scan for one layer (512 steps, 1 grid barrier each).
// Block bx owns output columns [bx*8, bx*8+8). Its 8 W_hat rows are staged in
// SMEM ONCE for the whole kernel. Per step, h (64x1024) is staged in 4 chunks
// of 256 k. Thread computes a 2(batch) x 2(col) tile; batches are (g, g+32)
// with g = tid>>2 so the 8 per-warp h-row groups hit distinct banks
// (g*H_PITCH mod 32 = g*4 : conflict-free).
// out points at d_out + layer*H; element (t,b,c) at (t*B+b)*2*H + c.
// ============================================================================
__global__ void scan_kernel(const float* __restrict__ What,
                            float* __restrict__ out)
{
    extern __shared__ float smem[];
    float* Wsh = smem;                  // [8][W_PITCH]
    float* hsh = smem + 8 * W_PITCH;    // [64][H_PITCH]

    const int tid   = threadIdx.x;
    const int cbase = blockIdx.x * 8;

    // Stage this block's 8 rows of W_hat (8 x 1024 floats = 32 KB), once.
    #pragma unroll
    for (int i = 0; i < 16; i++) {
        int idx = tid + i * SCAN_THREADS;   // 0..2047
        int r = idx >> 8;                   // 0..7
        int q = idx & 255;                  // float4 index within row
        float4 v = *(const float4*)&What[(long)(cbase + r) * H_SZ + q * 4];
        *(float4*)&Wsh[r * W_PITCH + q * 4] = v;
    }

    // Zero h buffer 0 (read at t=0): 65536 floats / 16384 threads = 1 float4.
    {
        int gt = blockIdx.x * SCAN_THREADS + tid;
        *(float4*)&g_h[0][gt * 4] = make_float4(0.f, 0.f, 0.f, 0.f);
    }
    grid_barrier();

    const int b0 = tid >> 2, b1 = b0 + 32;        // batch pair (bank-friendly)
    const int c0 = (tid & 3) * 2, c1 = c0 + 1;    // local col pair
    const int cg0 = cbase + c0, cg1 = cbase + c1;

    for (int t = 0; t < T_STEPS; t++) {
        const float* hin  = g_h[t & 1];
        float*       hout = g_h[(t + 1) & 1];

        float a00 = 0.f, a01 = 0.f, a10 = 0.f, a11 = 0.f;

        for (int kc = 0; kc < 4; kc++) {
            __syncthreads();   // hsh from previous chunk fully consumed
            // stage h[0:64][kc*256 : kc*256+256]  (64 KB)
            #pragma unroll
            for (int i = 0; i < 32; i++) {
                int idx = tid + i * SCAN_THREADS;   // 0..4095
                int r = idx >> 6;                   // 0..63
                int q = idx & 63;                   // float4 index
                float4 v = *(const float4*)&hin[r * H_SZ + kc * 256 + q * 4];
                *(float4*)&hsh[r * H_PITCH + q * 4] = v;
            }
            __syncthreads();

            const float* wrow0 = &Wsh[c0 * W_PITCH + kc * 256];
            const float* wrow1 = wrow0 + W_PITCH;
            const float* hrow0 = &hsh[b0 * H_PITCH];
            const float* hrow1 = &hsh[b1 * H_PITCH];

            #pragma unroll 4
            for (int k4 = 0; k4 < 64; k4++) {
                float4 ha = *(const float4*)&hrow0[k4 * 4];
                float4 hb = *(const float4*)&hrow1[k4 * 4];
                float4 w0 = *(const float4*)&wrow0[k4 * 4];
                float4 w1 = *(const float4*)&wrow1[k4 * 4];
                a00 += ha.x * w0.x + ha.y * w0.y + ha.z * w0.z + ha.w * w0.w;
                a01 += ha.x * w1.x + ha.y * w1.y + ha.z * w1.z + ha.w * w1.w;
                a10 += hb.x * w0.x + hb.y * w0.y + hb.z * w0.z + hb.w * w0.w;
                a11 += hb.x * w1.x + hb.y * w1.y + hb.z * w1.z + hb.w * w1.w;
            }
        }

        // finalize: h_new = 0.5*h + 0.5*tanh(acc + U[t])
        const float* Ut = &g_U[(long)t * (B_SZ * H_SZ)];

        float p00 = a00 + Ut[b0 * H_SZ + cg0];
        float p01 = a01 + Ut[b0 * H_SZ + cg1];
        float p10 = a10 + Ut[b1 * H_SZ + cg0];
        float p11 = a11 + Ut[b1 * H_SZ + cg1];

        float h00 = (1.f - ALPHA) * hin[b0 * H_SZ + cg0] + ALPHA * tanhf(p00);
        float h01 = (1.f - ALPHA) * hin[b0 * H_SZ + cg1] + ALPHA * tanhf(p01);
        float h10 = (1.f - ALPHA) * hin[b1 * H_SZ + cg0] + ALPHA * tanhf(p10);
        float h11 = (1.f - ALPHA) * hin[b1 * H_SZ + cg1] + ALPHA * tanhf(p11);

        hout[b0 * H_SZ + cg0] = h00;
        hout[b0 * H_SZ + cg1] = h01;
        hout[b1 * H_SZ + cg0] = h10;
        hout[b1 * H_SZ + cg1] = h11;

        long ob0 = ((long)(t * B_SZ + b0)) * 2 * H_SZ;
        long ob1 = ((long)(t * B_SZ + b1)) * 2 * H_SZ;
        out[ob0 + cg0] = h00;
        out[ob0 + cg1] = h01;
        out[ob1 + cg0] = h10;
        out[ob1 + cg1] = h11;

        grid_barrier();   // hout fully committed before next step reads it
    }
}

// ============================================================================
// Host launch: 4 kernel nodes total (tiny graph -> no 2MB upload-pool leak).
// U0 gemm -> scan0 (persistent) -> U1 gemm -> scan1 (persistent).
// ============================================================================
extern "C" void kernel_launch(void* const* d_in, const int* in_sizes, int n_in,
                              void* d_out, int out_size)
{
    (void)in_sizes; (void)n_in; (void)out_size;
    const float* x     = (const float*)d_in[0];   // [T,B,I]
    const float* Win0  = (const float*)d_in[1];   // [H,I]
    const float* What0 = (const float*)d_in[2];   // [H,H]
    const float* Win1  = (const float*)d_in[3];   // [H,H]
    const float* What1 = (const float*)d_in[4];   // [H,H]
    float* out = (float*)d_out;                   // [T,B,2,H]

    cudaFuncSetAttribute(scan_kernel,
                         cudaFuncAttributeMaxDynamicSharedMemorySize,
                         SMEM_SCAN_BYTES);

    dim3 ggrid(H_SZ / 64, (T_STEPS * B_SZ) / 64);   // (16, 512)

    // ---- layer 0 ----
    gemm_abT<<<ggrid, 128>>>(x, I_SZ, Win0, I_SZ);          // U0 = x @ W_in0^T
    scan_kernel<<<SCAN_BLOCKS, SCAN_THREADS, SMEM_SCAN_BYTES>>>(What0, out);

    // ---- layer 1 ----
    gemm_abT<<<ggrid, 128>>>(out, 2 * H_SZ, Win1, H_SZ);    // U1 = e0 @ W_in1^T
    scan_kernel<<<SCAN_BLOCKS, SCAN_THREADS, SMEM_SCAN_BYTES>>>(What1, out + H_SZ);
}

// round 5
// speedup vs baseline: 2.3567x; 2.3567x over previous
#include <cuda_runtime.h>
#include <math.h>

#define T_STEPS 512
#define B_SZ    64
#define I_SZ    128
#define H_SZ    1024
#define ALPHA   0.5f

#define SCAN_BLOCKS  128
#define SCAN_THREADS 512
#define W_PITCH  1028   // 1024 + 4 pad (floats)
#define H_PITCH  260    // 256 + 4 pad (floats)

#define WSH_FLOATS   (8 * W_PITCH)           // 8224
#define HSH_FLOATS   (64 * H_PITCH)          // 16640
#define RED_FLOATS   (4 * 512)               // slot-major partial buffer
#define SMEM_SCAN_BYTES ((WSH_FLOATS + HSH_FLOATS + RED_FLOATS) * 4)

// ---- scratch (no allocations allowed; __device__ globals are the sanctioned path)
__device__ float g_U[(long)T_STEPS * B_SZ * H_SZ];   // 134 MB, reused for U0 then U1
__device__ float g_h[2][B_SZ * H_SZ];                // double-buffered recurrent state
__device__ unsigned long long g_bar;                 // monotonic grid-barrier counter

// ============================================================================
// Software grid barrier. All SCAN_BLOCKS=128 blocks of the lone running kernel
// are co-resident (128 <= SM count, 1 block/SM by smem), so this cannot
// deadlock. Monotonic counter -> no reset, deterministic across graph replays.
// ============================================================================
__device__ __forceinline__ void grid_barrier() {
    __syncthreads();
    if (threadIdx.x == 0) {
        __threadfence();
        unsigned long long prev = atomicAdd(&g_bar, 1ULL);
        unsigned long long target =
            (prev / SCAN_BLOCKS + 1ULL) * (unsigned long long)SCAN_BLOCKS;
        while (*((volatile unsigned long long*)&g_bar) < target) { }
        __threadfence();
    }
    __syncthreads();
}

// ============================================================================
// GEMM: g_U[m][n] = sum_k A[m*lda + k] * B[n*K + k]   (C = A @ B^T)
// 64x64 tile, K-chunk 32, 128 threads, 8x4 register tile per thread.
// ============================================================================
__global__ void gemm_abT(const float* __restrict__ A, int lda,
                         const float* __restrict__ Bm, int K)
{
    __shared__ float Ast[32][68];
    __shared__ float Bst[32][68];
    const int tid = threadIdx.x;
    const int m0 = blockIdx.y * 64;
    const int n0 = blockIdx.x * 64;
    const int tx = tid & 15;
    const int ty = tid >> 4;

    float acc[8][4] = {};

    for (int k0 = 0; k0 < K; k0 += 32) {
        #pragma unroll
        for (int i = 0; i < 4; i++) {
            int idx = tid + i * 128;
            int row = idx >> 3;
            int kq  = idx & 7;
            float4 v = *(const float4*)&A[(long)(m0 + row) * lda + k0 + kq * 4];
            Ast[kq * 4 + 0][row] = v.x;
            Ast[kq * 4 + 1][row] = v.y;
            Ast[kq * 4 + 2][row] = v.z;
            Ast[kq * 4 + 3][row] = v.w;
            float4 w = *(const float4*)&Bm[(long)(n0 + row) * K + k0 + kq * 4];
            Bst[kq * 4 + 0][row] = w.x;
            Bst[kq * 4 + 1][row] = w.y;
            Bst[kq * 4 + 2][row] = w.z;
            Bst[kq * 4 + 3][row] = w.w;
        }
        __syncthreads();
        #pragma unroll
        for (int k = 0; k < 32; k++) {
            float4 a0 = *(const float4*)&Ast[k][ty * 8];
            float4 a1 = *(const float4*)&Ast[k][ty * 8 + 4];
            float4 bv = *(const float4*)&Bst[k][tx * 4];
            float a[8] = {a0.x, a0.y, a0.z, a0.w, a1.x, a1.y, a1.z, a1.w};
            float b[4] = {bv.x, bv.y, bv.z, bv.w};
            #pragma unroll
            for (int i = 0; i < 8; i++)
                #pragma unroll
                for (int j = 0; j < 4; j++)
                    acc[i][j] += a[i] * b[j];
        }
        __syncthreads();
    }

    #pragma unroll
    for (int i = 0; i < 8; i++) {
        float4 o = make_float4(acc[i][0], acc[i][1], acc[i][2], acc[i][3]);
        *(float4*)&g_U[(long)(m0 + ty * 8 + i) * H_SZ + n0 + tx * 4] = o;
    }
}

// ============================================================================
// Persistent sequential scan for one layer (512 steps, 1 grid barrier each).
// Block bx owns output columns [bx*8, bx*8+8). 512 threads = 4 K-groups of
// 128: group g computes the same 2(batch)x2(col) tile over K quarter g
// (64 k per 256-k chunk, 4 chunks). Partials combined through a slot-major
// smem buffer; finalize spread over all 512 threads (one output each).
// W_hat rows staged once; h staged per-step in 4 chunks of 256 k.
// out points at d_out + layer*H; element (t,b,c) at (t*B+b)*2*H + c.
// ============================================================================
__global__ void scan_kernel(const float* __restrict__ What,
                            float* __restrict__ out)
{
    extern __shared__ float smem[];
    float* Wsh = smem;                           // [8][W_PITCH]
    float* hsh = smem + WSH_FLOATS;              // [64][H_PITCH]
    float* red = smem + WSH_FLOATS + HSH_FLOATS; // [4 slots][512] s-major

    const int tid   = threadIdx.x;
    const int cbase = blockIdx.x * 8;

    // Stage this block's 8 rows of W_hat (2048 float4 / 512 threads = 4 each)
    #pragma unroll
    for (int i = 0; i < 4; i++) {
        int idx = tid + i * SCAN_THREADS;   // 0..2047
        int r = idx >> 8;
        int q = idx & 255;
        float4 v = *(const float4*)&What[(long)(cbase + r) * H_SZ + q * 4];
        *(float4*)&Wsh[r * W_PITCH + q * 4] = v;
    }

    // Zero h buffer 0 (65536 floats / 65536 threads = 1 each)
    g_h[0][blockIdx.x * SCAN_THREADS + tid] = 0.f;
    grid_barrier();

    const int grp  = tid >> 7;          // K-group 0..3
    const int ltid = tid & 127;
    const int b0 = ltid >> 2, b1 = b0 + 32;       // batch pair (bank-friendly)
    const int c0 = (ltid & 3) * 2, c1 = c0 + 1;   // local col pair

    // finalize mapping: one output (fb, fc) per thread
    const int fb   = tid >> 3;          // 0..63
    const int fcl  = tid & 7;           // 0..7
    const int fltid = ((fb & 31) << 2) | (fcl >> 1);
    const int fs    = ((fb >> 5) << 1) | (fcl & 1);
    const int fcg   = cbase + fcl;

    for (int t = 0; t < T_STEPS; t++) {
        const float* hin  = g_h[t & 1];
        float*       hout = g_h[(t + 1) & 1];

        float a00 = 0.f, a01 = 0.f, a10 = 0.f, a11 = 0.f;

        for (int kc = 0; kc < 4; kc++) {
            __syncthreads();   // hsh from previous chunk fully consumed
            // stage h[0:64][kc*256 : kc*256+256]  (4096 float4 / 512 thr = 8)
            #pragma unroll
            for (int i = 0; i < 8; i++) {
                int idx = tid + i * SCAN_THREADS;   // 0..4095
                int r = idx >> 6;
                int q = idx & 63;
                float4 v = *(const float4*)&hin[r * H_SZ + kc * 256 + q * 4];
                *(float4*)&hsh[r * H_PITCH + q * 4] = v;
            }
            __syncthreads();

            const float* wrow0 = &Wsh[c0 * W_PITCH + kc * 256 + grp * 64];
            const float* wrow1 = wrow0 + W_PITCH;
            const float* hrow0 = &hsh[b0 * H_PITCH + grp * 64];
            const float* hrow1 = &hsh[b1 * H_PITCH + grp * 64];

            #pragma unroll 4
            for (int k4 = 0; k4 < 16; k4++) {
                float4 ha = *(const float4*)&hrow0[k4 * 4];
                float4 hb = *(const float4*)&hrow1[k4 * 4];
                float4 w0 = *(const float4*)&wrow0[k4 * 4];
                float4 w1 = *(const float4*)&wrow1[k4 * 4];
                a00 += ha.x * w0.x + ha.y * w0.y + ha.z * w0.z + ha.w * w0.w;
                a01 += ha.x * w1.x + ha.y * w1.y + ha.z * w1.z + ha.w * w1.w;
                a10 += hb.x * w0.x + hb.y * w0.y + hb.z * w0.z + hb.w * w0.w;
                a11 += hb.x * w1.x + hb.y * w1.y + hb.z * w1.z + hb.w * w1.w;
            }
        }

        // publish partials: red[slot][grp*128 + ltid], slot-major (no conflicts)
        {
            int base = grp * 128 + ltid;
            red[0 * 512 + base] = a00;
            red[1 * 512 + base] = a01;
            red[2 * 512 + base] = a10;
            red[3 * 512 + base] = a11;
        }
        __syncthreads();

        // finalize: each thread sums its output's 4 partials
        {
            const float* rs = &red[fs * 512 + fltid];
            float sum = rs[0] + rs[128] + rs[256] + rs[384];

            const float* Ut = &g_U[(long)t * (B_SZ * H_SZ)];
            float pre = sum + Ut[fb * H_SZ + fcg];
            float hv = (1.f - ALPHA) * hin[fb * H_SZ + fcg] + ALPHA * tanhf(pre);
            hout[fb * H_SZ + fcg] = hv;
            out[((long)(t * B_SZ + fb)) * 2 * H_SZ + fcg] = hv;
        }

        grid_barrier();   // hout fully committed before next step reads it
    }
}

// ============================================================================
// Host launch: 4 kernel nodes total (tiny graph -> no upload-pool violation).
// ============================================================================
extern "C" void kernel_launch(void* const* d_in, const int* in_sizes, int n_in,
                              void* d_out, int out_size)
{
    (void)in_sizes; (void)n_in; (void)out_size;
    const float* x     = (const float*)d_in[0];   // [T,B,I]
    const float* Win0  = (const float*)d_in[1];   // [H,I]
    const float* What0 = (const float*)d_in[2];   // [H,H]
    const float* Win1  = (const float*)d_in[3];   // [H,H]
    const float* What1 = (const float*)d_in[4];   // [H,H]
    float* out = (float*)d_out;                   // [T,B,2,H]

    cudaFuncSetAttribute(scan_kernel,
                         cudaFuncAttributeMaxDynamicSharedMemorySize,
                         SMEM_SCAN_BYTES);

    dim3 ggrid(H_SZ / 64, (T_STEPS * B_SZ) / 64);   // (16, 512)

    // ---- layer 0 ----
    gemm_abT<<<ggrid, 128>>>(x, I_SZ, Win0, I_SZ);          // U0 = x @ W_in0^T
    scan_kernel<<<SCAN_BLOCKS, SCAN_THREADS, SMEM_SCAN_BYTES>>>(What0, out);

    // ---- layer 1 ----
    gemm_abT<<<ggrid, 128>>>(out, 2 * H_SZ, Win1, H_SZ);    // U1 = e0 @ W_in1^T
    scan_kernel<<<SCAN_BLOCKS, SCAN_THREADS, SMEM_SCAN_BYTES>>>(What1, out + H_SZ);
}